// round 1
// baseline (speedup 1.0000x reference)
#include <cuda_runtime.h>
#include <math_constants.h>

#define SEQ    8192
#define DMODEL 1024
#define DHEAD  128

typedef unsigned long long u64;

// ---------- packed f32x2 helpers (FFMA2 path: 2x fp32 FMA rate on sm_103a) ----------
__device__ __forceinline__ u64 pack2(float a, float b) {
    u64 r; asm("mov.b64 %0, {%1, %2};" : "=l"(r) : "f"(a), "f"(b)); return r;
}
__device__ __forceinline__ void unpack2(u64 v, float &a, float &b) {
    asm("mov.b64 {%0, %1}, %2;" : "=f"(a), "=f"(b) : "l"(v));
}
__device__ __forceinline__ void fma2(u64 &d, u64 a, u64 b) {
    asm("fma.rn.f32x2 %0, %1, %2, %0;" : "+l"(d) : "l"(a), "l"(b));
}
__device__ __forceinline__ void mul2(u64 &d, u64 a) {
    asm("mul.rn.f32x2 %0, %0, %1;" : "+l"(d) : "l"(a));
}

// ---------- scratch (device globals: no allocation allowed) ----------
__device__ float g_Q[SEQ * DHEAD];
__device__ float g_K[SEQ * DHEAD];
__device__ float g_V[SEQ * DHEAD];

// =====================================================================
// Kernel 1: QKV projection.  C[M,128] = X[M,1024] @ W[128,1024]^T
// BM=64, BN=128(all), BK=32, 256 threads, per-thread 4x8 via f32x2 k-pairs.
// =====================================================================
#define PBK  32
#define PSTR (PBK + 2)   // 34 (even -> 8B-aligned k-pair loads)

__global__ __launch_bounds__(256, 2)
void qkv_proj_kernel(const float* __restrict__ X,
                     const float* __restrict__ Wq,
                     const float* __restrict__ Wk,
                     const float* __restrict__ Wv)
{
    __shared__ __align__(16) float Xs[64][PSTR];
    __shared__ __align__(16) float Ws[128][PSTR];

    const int tid = threadIdx.x;
    const int tr  = tid >> 4;    // 0..15
    const int tc  = tid & 15;    // 0..15

    const int mblk = blockIdx.x * 64;
    const int w    = blockIdx.y;
    const float* __restrict__ W = (w == 0) ? Wq : (w == 1) ? Wk : Wv;
    float* __restrict__ C       = (w == 0) ? g_Q : (w == 1) ? g_K : g_V;
    const float scale = (w == 0) ? 0.08838834764831845f : 1.0f;  // 1/sqrt(128) folded into Q

    u64 acc[4][8];
    #pragma unroll
    for (int i = 0; i < 4; ++i)
        #pragma unroll
        for (int j = 0; j < 8; ++j) acc[i][j] = 0ull;   // (0.f,0.f)

    for (int k0 = 0; k0 < DMODEL; k0 += PBK) {
        // X tile 64x32 (512 float4)
        #pragma unroll
        for (int it = 0; it < 2; ++it) {
            int f = tid + it * 256;
            int row = f >> 3, c = (f & 7) * 4;
            const float4 v = *(const float4*)&X[(mblk + row) * DMODEL + k0 + c];
            float* dst = &Xs[row][c];
            *(float2*)dst       = make_float2(v.x, v.y);
            *(float2*)(dst + 2) = make_float2(v.z, v.w);
        }
        // W tile 128x32 (1024 float4)
        #pragma unroll
        for (int it = 0; it < 4; ++it) {
            int f = tid + it * 256;
            int row = f >> 3, c = (f & 7) * 4;
            const float4 v = *(const float4*)&W[row * DMODEL + k0 + c];
            float* dst = &Ws[row][c];
            *(float2*)dst       = make_float2(v.x, v.y);
            *(float2*)(dst + 2) = make_float2(v.z, v.w);
        }
        __syncthreads();

        #pragma unroll 8
        for (int kk = 0; kk < PBK; kk += 2) {
            u64 xv[4], wv[8];
            #pragma unroll
            for (int i = 0; i < 4; ++i)  xv[i]  = *(const u64*)&Xs[tr * 4 + i][kk];
            #pragma unroll
            for (int jj = 0; jj < 8; ++jj) wv[jj] = *(const u64*)&Ws[tc + 16 * jj][kk];
            #pragma unroll
            for (int i = 0; i < 4; ++i)
                #pragma unroll
                for (int jj = 0; jj < 8; ++jj)
                    fma2(acc[i][jj], xv[i], wv[jj]);
        }
        __syncthreads();
    }

    #pragma unroll
    for (int i = 0; i < 4; ++i) {
        int m = mblk + tr * 4 + i;
        #pragma unroll
        for (int jj = 0; jj < 8; ++jj) {
            float a, b; unpack2(acc[i][jj], a, b);
            C[m * DHEAD + tc + 16 * jj] = (a + b) * scale;
        }
    }
}

// =====================================================================
// Kernel 2: causal flash attention, fp32.
// 128 CTAs x 256 threads. Each CTA: paired 32-row q-blocks (b, 255-b),
// rows interleaved per-thread for load balance. BN=64 keys per tile.
// =====================================================================
#define QSTR 130
#define KSTR 130
#define VSTR 132
#define PPAD 65

struct SmemA {
    float Qs[64][QSTR];
    float Ks[64][KSTR];
    float Vs[64][VSTR];
    float Ps[64][PPAD];
};

template<int I0>
__device__ __forceinline__ void process_tile(SmemA& S, int j, const int grow[4],
                                             const int mloc[4],
                                             u64 O2[4][4], float mrow[4], float lrow[4],
                                             int tr, int tc)
{
    // ---- S = Q K^T (this thread: rows I0..3, cols tc+16*jj) ----
    u64 acc[4][4];
    #pragma unroll
    for (int i = I0; i < 4; ++i)
        #pragma unroll
        for (int jj = 0; jj < 4; ++jj) acc[i][jj] = 0ull;

    #pragma unroll 8
    for (int k = 0; k < DHEAD; k += 2) {
        u64 qv[4], kv[4];
        #pragma unroll
        for (int i = I0; i < 4; ++i)  qv[i]  = *(const u64*)&S.Qs[mloc[i]][k];
        #pragma unroll
        for (int jj = 0; jj < 4; ++jj) kv[jj] = *(const u64*)&S.Ks[tc + 16 * jj][k];
        #pragma unroll
        for (int i = I0; i < 4; ++i)
            #pragma unroll
            for (int jj = 0; jj < 4; ++jj)
                fma2(acc[i][jj], qv[i], kv[jj]);
    }

    // ---- online softmax update ----
    #pragma unroll
    for (int i = I0; i < 4; ++i) {
        float sv[4];
        float tmax = -CUDART_INF_F;
        #pragma unroll
        for (int jj = 0; jj < 4; ++jj) {
            float a, b; unpack2(acc[i][jj], a, b);
            float s = a + b;                        // Q pre-scaled by 1/sqrt(d)
            int col = j * 64 + tc + 16 * jj;
            s = (col <= grow[i]) ? s : -1e30f;      // causal mask
            sv[jj] = s;
            tmax = fmaxf(tmax, s);
        }
        #pragma unroll
        for (int mk = 8; mk >= 1; mk >>= 1)
            tmax = fmaxf(tmax, __shfl_xor_sync(0xffffffffu, tmax, mk));

        float mnew  = fmaxf(mrow[i], tmax);
        float alpha = __expf(mrow[i] - mnew);
        mrow[i] = mnew;

        float psum = 0.f;
        float pv[4];
        #pragma unroll
        for (int jj = 0; jj < 4; ++jj) {
            float p = __expf(sv[jj] - mnew);
            pv[jj] = p; psum += p;
        }
        #pragma unroll
        for (int mk = 8; mk >= 1; mk >>= 1)
            psum += __shfl_xor_sync(0xffffffffu, psum, mk);
        lrow[i] = lrow[i] * alpha + psum;

        u64 a2 = pack2(alpha, alpha);
        #pragma unroll
        for (int dj = 0; dj < 4; ++dj) mul2(O2[i][dj], a2);

        #pragma unroll
        for (int jj = 0; jj < 4; ++jj)
            S.Ps[mloc[i]][tc + 16 * jj] = pv[jj];
    }
    __syncthreads();

    // ---- O += P V  (this thread: rows I0..3, d = tc*8 .. tc*8+7) ----
    #pragma unroll 4
    for (int n = 0; n < 64; ++n) {
        const float4 va = *(const float4*)&S.Vs[n][tc * 8];
        const float4 vb = *(const float4*)&S.Vs[n][tc * 8 + 4];
        u64 v2[4];
        v2[0] = pack2(va.x, va.y); v2[1] = pack2(va.z, va.w);
        v2[2] = pack2(vb.x, vb.y); v2[3] = pack2(vb.z, vb.w);
        #pragma unroll
        for (int i = I0; i < 4; ++i) {
            float p = S.Ps[mloc[i]][n];
            u64 p2 = pack2(p, p);
            #pragma unroll
            for (int dj = 0; dj < 4; ++dj)
                fma2(O2[i][dj], p2, v2[dj]);
        }
    }
}

__global__ __launch_bounds__(256, 1)
void attn_kernel(float* __restrict__ Out)
{
    extern __shared__ __align__(16) char smem_raw[];
    SmemA& S = *reinterpret_cast<SmemA*>(smem_raw);

    const int tid = threadIdx.x;
    const int tr  = tid >> 4;   // 0..15
    const int tc  = tid & 15;   // 0..15
    const int b   = blockIdx.x; // 0..127

    const int q0 = b * 32;           // early q-block
    const int q1 = (255 - b) * 32;   // late q-block (paired for balance)

    const int mloc[4] = {2 * tr, 2 * tr + 1, 32 + 2 * tr, 33 + 2 * tr};
    int grow[4];
    grow[0] = q0 + 2 * tr; grow[1] = q0 + 2 * tr + 1;
    grow[2] = q1 + 2 * tr; grow[3] = q1 + 2 * tr + 1;

    // load Q (local rows 0..31 -> q0, 32..63 -> q1); already scaled by 1/sqrt(d)
    #pragma unroll
    for (int it = 0; it < 8; ++it) {
        int f = tid + it * 256;
        int lr = f >> 5, c = (f & 31) * 4;
        int gr = (lr < 32) ? (q0 + lr) : (q1 + lr - 32);
        const float4 v = *(const float4*)&g_Q[gr * DHEAD + c];
        float* dst = &S.Qs[lr][c];
        *(float2*)dst       = make_float2(v.x, v.y);
        *(float2*)(dst + 2) = make_float2(v.z, v.w);
    }

    u64 O2[4][4];
    #pragma unroll
    for (int i = 0; i < 4; ++i)
        #pragma unroll
        for (int j = 0; j < 4; ++j) O2[i][j] = 0ull;
    float mrow[4] = {-CUDART_INF_F, -CUDART_INF_F, -CUDART_INF_F, -CUDART_INF_F};
    float lrow[4] = {0.f, 0.f, 0.f, 0.f};

    const int t0 = (b + 2) >> 1;     // tiles with group0 still active
    const int t1 = (257 - b) >> 1;   // total tiles (group1 extent)

    for (int j = 0; j < t1; ++j) {
        // load K/V tile (64 keys x 128)
        #pragma unroll
        for (int it = 0; it < 8; ++it) {
            int f = tid + it * 256;
            int r = f >> 5, c = (f & 31) * 4;
            int g = (j * 64 + r) * DHEAD + c;
            const float4 kv = *(const float4*)&g_K[g];
            float* kd = &S.Ks[r][c];
            *(float2*)kd       = make_float2(kv.x, kv.y);
            *(float2*)(kd + 2) = make_float2(kv.z, kv.w);
            *(float4*)&S.Vs[r][c] = *(const float4*)&g_V[g];
        }
        __syncthreads();

        if (j < t0) process_tile<0>(S, j, grow, mloc, O2, mrow, lrow, tr, tc);
        else        process_tile<2>(S, j, grow, mloc, O2, mrow, lrow, tr, tc);
        __syncthreads();
    }

    // epilogue: normalize and store
    #pragma unroll
    for (int i = 0; i < 4; ++i) {
        float inv = 1.0f / lrow[i];
        float o[8];
        #pragma unroll
        for (int dj = 0; dj < 4; ++dj) {
            float a, c; unpack2(O2[i][dj], a, c);
            o[2 * dj] = a * inv; o[2 * dj + 1] = c * inv;
        }
        float4* dst = (float4*)&Out[grow[i] * DHEAD + tc * 8];
        dst[0] = make_float4(o[0], o[1], o[2], o[3]);
        dst[1] = make_float4(o[4], o[5], o[6], o[7]);
    }
}

// =====================================================================
extern "C" void kernel_launch(void* const* d_in, const int* in_sizes, int n_in,
                              void* d_out, int out_size)
{
    (void)in_sizes; (void)n_in; (void)out_size;
    const float* X  = (const float*)d_in[0];
    const float* Wq = (const float*)d_in[1];
    const float* Wk = (const float*)d_in[2];
    const float* Wv = (const float*)d_in[3];
    float* Out = (float*)d_out;

    dim3 pg(SEQ / 64, 3);
    qkv_proj_kernel<<<pg, 256>>>(X, Wq, Wk, Wv);

    const int smem = (int)sizeof(SmemA);
    cudaFuncSetAttribute(attn_kernel, cudaFuncAttributeMaxDynamicSharedMemorySize, smem);
    attn_kernel<<<128, 256, smem>>>(Out);
}